// round 17
// baseline (speedup 1.0000x reference)
#include <cuda_runtime.h>
#include <math.h>
#include <stdint.h>

#define BB 16
#define SEQL 1025
#define EMB 384
#define HDS 6
#define HD 64
#define NF 32
#define ROWS (BB*SEQL)
#define BHN (BB*HDS)
#define NT 17
#define NPAD (NT*64)

__device__ float g_q[(size_t)BHN*SEQL*HD];
__device__ float g_ao[(size_t)ROWS*EMB];
__device__ float g_cos[SEQL*HDS*NF];
__device__ float g_sin[SEQL*HDS*NF];
__device__ float g_freqs[HDS*NF*2];
__device__ uint2    g_kp[(size_t)BHN*NT*2304];
// V pair-packed: uint2 slot [col*36 + ks*4 + tig] = (V[8ks+tig][col], V[8ks+tig+4][col])
__device__ uint32_t g_vp[(size_t)BHN*NT*4608];
__device__ uint4    g_wp[(size_t)4*6*12*1280];

// ===================== mma.sync helpers =====================
__device__ __forceinline__ uint32_t f2tf32(float x) {
    uint32_t r;
    asm("cvt.rna.tf32.f32 %0, %1;" : "=r"(r) : "f"(x));
    return r;
}
__device__ __forceinline__ void mma_tf32(float* d, const uint32_t* a,
                                         uint32_t b0, uint32_t b1) {
    asm volatile(
        "mma.sync.aligned.m16n8k8.row.col.f32.tf32.tf32.f32 "
        "{%0,%1,%2,%3}, {%4,%5,%6,%7}, {%8,%9}, {%0,%1,%2,%3};"
        : "+f"(d[0]), "+f"(d[1]), "+f"(d[2]), "+f"(d[3])
        : "r"(a[0]), "r"(a[1]), "r"(a[2]), "r"(a[3]), "r"(b0), "r"(b1));
}
__device__ __forceinline__ uint32_t smem_to_u32(const void* p) {
    uint32_t a;
    asm("{ .reg .u64 t; cvta.to.shared.u64 t, %1; cvt.u32.u64 %0, t; }" : "=r"(a) : "l"(p));
    return a;
}
#define CP16(dst, src) \
    asm volatile("cp.async.cg.shared.global [%0], [%1], 16;" :: "r"(dst), "l"(src))
#define CP16Z(dst, src, sz) \
    asm volatile("cp.async.cg.shared.global [%0], [%1], 16, %2;" :: "r"(dst), "l"(src), "r"(sz))
#define CP_COMMIT() asm volatile("cp.async.commit_group;" ::: "memory")
#define CP_WAIT0()  asm volatile("cp.async.wait_group 0;" ::: "memory")
#define CP_WAIT1()  asm volatile("cp.async.wait_group 1;" ::: "memory")

// ===================== init (bit-matched constants) =====================
__device__ __forceinline__ float erfinv_xla(float x) {
    float w = -log1pf(-__fmul_rn(x, x));
    float p;
    if (w < 5.0f) {
        w = w - 2.5f;
        p = 2.81022636e-08f;
        p = fmaf(p, w, 3.43273939e-07f);
        p = fmaf(p, w, -3.5233877e-06f);
        p = fmaf(p, w, -4.39150654e-06f);
        p = fmaf(p, w, 0.00021858087f);
        p = fmaf(p, w, -0.00125372503f);
        p = fmaf(p, w, -0.00417768164f);
        p = fmaf(p, w, 0.246640727f);
        p = fmaf(p, w, 1.50140941f);
    } else {
        w = sqrtf(w) - 3.0f;
        p = -0.000200214257f;
        p = fmaf(p, w, 0.000100950558f);
        p = fmaf(p, w, 0.00134934322f);
        p = fmaf(p, w, -0.00367342844f);
        p = fmaf(p, w, 0.00573950773f);
        p = fmaf(p, w, -0.0076224613f);
        p = fmaf(p, w, 0.00943887047f);
        p = fmaf(p, w, 1.00167406f);
        p = fmaf(p, w, 2.83297682f);
    }
    return p * x;
}

__global__ void init_freqs(float inv_g) {
    int n = threadIdx.x;
    if (n >= HDS * NF) return;
    float alpha0 = powf(inv_g, 1.0f);
    float alpha1 = powf(inv_g, 2.0f);
    float fi = (float)(n + 1);
    float z0 = fmodf(__fmul_rn(fi, alpha0), 1.0f);
    float z1 = fmodf(__fmul_rn(fi, alpha1), 1.0f);
    float d0 = erfinv_xla(__fmul_rn(2.0f, z0) - 1.0f);
    float d1 = erfinv_xla(__fmul_rn(2.0f, z1) - 1.0f);
    float nrm = sqrtf(__fadd_rn(__fmul_rn(d0, d0), __fmul_rn(d1, d1)));
    d0 = __fdiv_rn(d0, nrm);
    d1 = __fdiv_rn(d1, nrm);
    int f = n % NF;
    float t = __fmul_rn((float)f, (1.0f / 31.0f));
    float omega = __fmul_rn(0.1f, powf(10000.0f, t));
    g_freqs[n * 2 + 0] = __fmul_rn(d0, omega);
    g_freqs[n * 2 + 1] = __fmul_rn(d1, omega);
}

__global__ void init_trig() {
    int idx = blockIdx.x * blockDim.x + threadIdx.x;
    if (idx >= SEQL * HDS * NF) return;
    int s = idx / (HDS * NF);
    int r = idx % (HDS * NF);
    float c0 = 0.f, c1 = 0.f;
    if (s > 0) {
        int p = s - 1;
        int xi = p % 32, yi = p / 32;
        c0 = __fmul_rn(__fdiv_rn((float)xi, 31.0f), 2.0f) - 1.0f;
        c1 = __fmul_rn(__fdiv_rn((float)yi, 31.0f), 2.0f) - 1.0f;
    }
    float th = __fadd_rn(__fmul_rn(g_freqs[r * 2 + 0], c0), __fmul_rn(g_freqs[r * 2 + 1], c1));
    g_cos[idx] = cosf(th);
    g_sin[idx] = sinf(th);
}

// ===================== one-shot W pack =====================
__global__ void __launch_bounds__(256) pack_w_kernel(
    const float* __restrict__ Wq, const float* __restrict__ Wk,
    const float* __restrict__ Wv, const float* __restrict__ Wo)
{
    int idx = blockIdx.x * 256 + threadIdx.x;
    if (idx >= 4 * 72 * 256) return;
    int ks = idx & 3;
    int n = (idx >> 2) & 63;
    int r2 = idx >> 8;
    int mat = r2 / 72;
    int rem = r2 % 72;
    int cb = rem / 12, c2 = rem % 12;
    const float* W = (mat == 0) ? Wq : (mat == 1) ? Wk : (mat == 2) ? Wv : Wo;
    int colbase = cb * 64, k0 = c2 * 32;
    float wv[8];
#pragma unroll
    for (int j = 0; j < 8; j++)
        wv[j] = W[(size_t)(k0 + 8 * ks + j) * EMB + colbase + n];
    uint32_t hi[8], lo[8];
#pragma unroll
    for (int j = 0; j < 8; j++) {
        hi[j] = f2tf32(wv[j]);
        lo[j] = f2tf32(wv[j] - __uint_as_float(hi[j]));
    }
    uint4* dst = g_wp + (size_t)r2 * 1280 + n * 20 + ks * 4;
    dst[0] = make_uint4(hi[0], hi[4], lo[0], lo[4]);
    dst[1] = make_uint4(hi[1], hi[5], lo[1], lo[5]);
    dst[2] = make_uint4(hi[2], hi[6], lo[2], lo[6]);
    dst[3] = make_uint4(hi[3], hi[7], lo[3], lo[7]);
}

// ===================== tensorized GEMM v7: 128-row tiles ====================
// CTA tile 128x64, 128 thr; warp tile 64 rows x 32 cols (mt 0..3).
#define GBUF3_W 9728            // x 128*36=4608 + W 5120 words
#define GXW_OFF 4608
#define GEMM_SMEM (2 * GBUF3_W * 4)   // 77824 B

struct GemmAcc { float o[4][4][4]; };   // [mt][nb][j]

__device__ __forceinline__ int gemm_ncol(int wc, int nb) {
    return wc * 16 + (nb & 1) * 8 + (nb >> 1) * 32;
}

__device__ __forceinline__ void gemm_issue_v7(
    const float* src, const uint4* wp, int row0, int c2,
    uint32_t sbase, int buf, int tid)
{
    uint32_t base = sbase + (buf ? GBUF3_W * 4 : 0);
#pragma unroll
    for (int u = 0; u < 8; u++) {
        int idx = tid + 128 * u;
        int rr = idx >> 3, c4 = idx & 7;
        int gr = row0 + rr;
        int ok = (gr < ROWS);
        int gc = ok ? gr : (ROWS - 1);
        uint32_t dst = base + (rr * 36 + 4 * c4) * 4;
        const char* s = (const char*)(src + (size_t)gc * EMB + c2 * 32 + 4 * c4);
        CP16Z(dst, s, ok ? 16 : 0);
    }
    const char* ws = (const char*)(wp + (size_t)c2 * 1280);
    uint32_t wd = base + GXW_OFF * 4;
#pragma unroll
    for (int i = 0; i < 10; i++) {
        int off = (tid + 128 * i) * 16;
        CP16(wd + off, ws + off);
    }
}

__device__ __forceinline__ void gemm_core_v7(
    const float* __restrict__ src, const uint4* __restrict__ wp,
    int row0, float* sm, GemmAcc& A)
{
    int tid = threadIdx.x;
    int wid = tid >> 5, lane = tid & 31;
    int g = lane >> 2, tig = lane & 3;
    int wr = wid & 1, wc = wid >> 1;
    int wrow = wr * 64;
    uint32_t sbase = smem_to_u32(sm);

    gemm_issue_v7(src, wp, row0, 0, sbase, 0, tid);
    CP_COMMIT();

#pragma unroll
    for (int c2 = 0; c2 < 12; c2++) {
        if (c2 < 11) {
            gemm_issue_v7(src, wp, row0, c2 + 1, sbase, (c2 + 1) & 1, tid);
            CP_COMMIT();
            CP_WAIT1();
        } else {
            CP_WAIT0();
        }
        __syncthreads();

        float* xs = sm + ((c2 & 1) ? GBUF3_W : 0);
        uint4* Wp = (uint4*)(xs + GXW_OFF);
#pragma unroll
        for (int ks = 0; ks < 4; ks++) {
            uint32_t ahi[4][4];
#pragma unroll
            for (int mt = 0; mt < 4; mt++) {
                int rbase = wrow + mt * 16;
                ahi[mt][0] = f2tf32(xs[(rbase + g) * 36 + 8 * ks + tig]);
                ahi[mt][1] = f2tf32(xs[(rbase + g + 8) * 36 + 8 * ks + tig]);
                ahi[mt][2] = f2tf32(xs[(rbase + g) * 36 + 8 * ks + tig + 4]);
                ahi[mt][3] = f2tf32(xs[(rbase + g + 8) * 36 + 8 * ks + tig + 4]);
            }
#pragma unroll
            for (int nb = 0; nb < 4; nb++) {
                uint4 w4 = Wp[(gemm_ncol(wc, nb) + g) * 20 + ks * 4 + tig];
#pragma unroll
                for (int mt = 0; mt < 4; mt++) {
                    mma_tf32(A.o[mt][nb], ahi[mt], w4.x, w4.y);
                    mma_tf32(A.o[mt][nb], ahi[mt], w4.z, w4.w);
                }
            }
        }
        __syncthreads();
    }
}

__global__ void __launch_bounds__(128, 2) qkv_mma_kernel(const float* __restrict__ x)
{
    extern __shared__ float sm[];
    int tid = threadIdx.x;
    int wid = tid >> 5, lane = tid & 31;
    int g = lane >> 2, tig = lane & 3;
    int wr = wid & 1, wc = wid >> 1;
    int wrow = wr * 64;
    int rb = blockIdx.x, h = blockIdx.y, z = blockIdx.z;
    int row0 = rb * 128;
    const uint4* wp = g_wp + ((size_t)z * 6 + h) * 12 * 1280;

    GemmAcc A;
#pragma unroll
    for (int mt = 0; mt < 4; mt++)
#pragma unroll
        for (int nb = 0; nb < 4; nb++)
#pragma unroll
            for (int j = 0; j < 4; j++) A.o[mt][nb][j] = 0.f;

    gemm_core_v7(x, wp, row0, sm, A);

    if (z == 0) {
        // Q: RoPE (pair nb <-> nb+2 holds f and f+32), store fp32
#pragma unroll
        for (int mt = 0; mt < 4; mt++)
#pragma unroll
            for (int nb = 0; nb < 2; nb++)
#pragma unroll
                for (int jj = 0; jj < 4; jj++) {
                    int gr = row0 + wrow + mt * 16 + g + 8 * (jj >> 1);
                    if (gr >= ROWS) continue;
                    int b = gr / SEQL, s = gr % SEQL;
                    int f = wc * 16 + nb * 8 + 2 * tig + (jj & 1);
                    float cv = g_cos[(s * HDS + h) * NF + f];
                    float sv = g_sin[(s * HDS + h) * NF + f];
                    float lov = A.o[mt][nb][jj], hiv = A.o[mt][nb + 2][jj];
                    float* dst = g_q + ((size_t)(b * HDS + h) * SEQL + s) * HD;
                    dst[f]      = lov * cv - hiv * sv;
                    dst[f + 32] = lov * sv + hiv * cv;
                }
    } else if (z == 1) {
        // K: RoPE -> tf32 -> packed fragment layout
#pragma unroll
        for (int mt = 0; mt < 4; mt++)
#pragma unroll
            for (int nb = 0; nb < 2; nb++)
#pragma unroll
                for (int jj = 0; jj < 4; jj++) {
                    int gr = row0 + wrow + mt * 16 + g + 8 * (jj >> 1);
                    bool ok = (gr < ROWS);
                    int b = ok ? gr / SEQL : 0;
                    int s = ok ? gr % SEQL : 0;
                    int f = wc * 16 + nb * 8 + 2 * tig + (jj & 1);
                    float cv = g_cos[(s * HDS + h) * NF + f];
                    float sv = g_sin[(s * HDS + h) * NF + f];
                    float lov = A.o[mt][nb][jj], hiv = A.o[mt][nb + 2][jj];
                    uint32_t hA = f2tf32(lov * cv - hiv * sv);
                    uint32_t hB = f2tf32(lov * sv + hiv * cv);
                    uint32_t pA = __shfl_xor_sync(0xffffffffu, hA, 2);
                    uint32_t pB = __shfl_xor_sync(0xffffffffu, hB, 2);
                    if (ok && tig < 2) {
                        uint2* kb = g_kp + ((size_t)(b * HDS + h) * NT + (s >> 6)) * 2304
                                    + (s & 63) * 36;
                        int tigk = 2 * tig + (jj & 1);
                        int ksA = wc * 2 + nb;
                        kb[ksA * 4 + tigk]       = make_uint2(hA, pA);
                        kb[(ksA + 4) * 4 + tigk] = make_uint2(hB, pB);
                    }
                }
    } else {
        // V: tf32 -> pair-packed layout, scalar word writes
#pragma unroll
        for (int mt = 0; mt < 4; mt++)
#pragma unroll
            for (int nb = 0; nb < 4; nb++)
#pragma unroll
                for (int jj = 0; jj < 4; jj++) {
                    int gr = row0 + wrow + mt * 16 + g + 8 * (jj >> 1);
                    if (gr >= ROWS) continue;
                    int b = gr / SEQL, s = gr % SEQL;
                    int col = gemm_ncol(wc, nb) + 2 * tig + (jj & 1);
                    int r = s & 63;
                    int woff = 2 * (col * 36 + (r >> 3) * 4 + (r & 3)) + ((r & 7) >> 2);
                    uint32_t* vb = g_vp + ((size_t)(b * HDS + h) * NT + (s >> 6)) * 4608;
                    vb[woff] = f2tf32(A.o[mt][nb][jj]);
                }
    }
}

__global__ void __launch_bounds__(128, 2) proj_mma_kernel(
    const float* __restrict__ bo, float* __restrict__ out)
{
    extern __shared__ float sm[];
    int tid = threadIdx.x;
    int wid = tid >> 5, lane = tid & 31;
    int g = lane >> 2, tig = lane & 3;
    int wr = wid & 1, wc = wid >> 1;
    int wrow = wr * 64;
    int rb = blockIdx.x, cb = blockIdx.y;
    int row0 = rb * 128, colbase = cb * 64;
    const uint4* wp = g_wp + ((size_t)3 * 6 + cb) * 12 * 1280;

    GemmAcc A;
#pragma unroll
    for (int mt = 0; mt < 4; mt++)
#pragma unroll
        for (int nb = 0; nb < 4; nb++)
#pragma unroll
            for (int j = 0; j < 4; j++) A.o[mt][nb][j] = 0.f;

    gemm_core_v7(g_ao, wp, row0, sm, A);

#pragma unroll
    for (int mt = 0; mt < 4; mt++)
#pragma unroll
        for (int nb = 0; nb < 4; nb++)
#pragma unroll
            for (int jj = 0; jj < 4; jj++) {
                int gr = row0 + wrow + mt * 16 + g + 8 * (jj >> 1);
                if (gr >= ROWS) continue;
                int col = gemm_ncol(wc, nb) + 2 * tig + (jj & 1);
                out[(size_t)gr * EMB + colbase + col] = A.o[mt][nb][jj] + bo[colbase + col];
            }
}

// ===================== Flash attention (cp.async pipelined) =================
#define PS_OFF 0
#define KP_OFF 4352
#define V0_OFF 8960
#define V1_OFF 13568
#define ATTN_SMEM (18176 * 4)   // 72704 B

__global__ void __launch_bounds__(128, 3) attn_mma_kernel() {
    extern __shared__ float sm[];
    float* Ps = sm + PS_OFF;
    uint32_t sbase = smem_to_u32(sm);

    int tid = threadIdx.x;
    int wid = tid >> 5, lane = tid & 31;
    int g = lane >> 2, tig = lane & 3;
    int wrow = wid * 16;
    int qb = blockIdx.x, bh = blockIdx.y;

    const float* Q = g_q + (size_t)bh * SEQL * HD;
    const char* gk = (const char*)(g_kp + (size_t)bh * NT * 2304);
    const char* gv = (const char*)(g_vp + (size_t)bh * NT * 4608);

    const uint32_t KPA = sbase + KP_OFF * 4;
    const uint32_t VA[2] = { sbase + V0_OFF * 4, sbase + V1_OFF * 4 };

#pragma unroll
    for (int i = 0; i < 9; i++) {
        int off = (tid + 128 * i) * 16;
        CP16(KPA + off, gk + off);
        CP16(VA[0] + off, gv + off);
    }
    CP_COMMIT();

#pragma unroll
    for (int u = 0; u < 8; u++) {
        int idx = tid + 128 * u;
        int rr = idx >> 4, c4 = idx & 15;
        int s = qb * 64 + rr;
        float4 v = make_float4(0.f, 0.f, 0.f, 0.f);
        if (s < SEQL) v = *(const float4*)(Q + (size_t)s * HD + c4 * 4);
        v.x *= 0.125f; v.y *= 0.125f; v.z *= 0.125f; v.w *= 0.125f;
        *(float4*)(Ps + rr * 68 + c4 * 4) = v;
    }
    __syncthreads();

    uint32_t qhi[8][4];
#pragma unroll
    for (int ks = 0; ks < 8; ks++) {
#pragma unroll
        for (int j = 0; j < 4; j++) {
            int rr = wrow + g + (j & 1) * 8;
            int cc = 8 * ks + tig + (j >> 1) * 4;
            qhi[ks][j] = f2tf32(Ps[rr * 68 + cc]);
        }
    }

    float o[8][4] = {};
    float m0 = -INFINITY, m1 = -INFINITY, l0 = 0.f, l1 = 0.f;

    for (int t = 0; t < NT; t++) {
        CP_WAIT0();
        __syncthreads();

        if (t < NT - 1) {
            const char* vsrc = gv + (size_t)(t + 1) * 4608 * 4;
            uint32_t vdst = VA[(t + 1) & 1];
#pragma unroll
            for (int i = 0; i < 9; i++) {
                int off = (tid + 128 * i) * 16;
                CP16(vdst + off, vsrc + off);
            }
            CP_COMMIT();
        }

        uint2* Kp = (uint2*)(sm + KP_OFF);
        float s_[8][4] = {};
#pragma unroll
        for (int ks = 0; ks < 8; ks++) {
#pragma unroll
            for (int nb = 0; nb < 8; nb++) {
                uint2 kk = Kp[(nb * 8 + g) * 36 + ks * 4 + tig];
                mma_tf32(s_[nb], qhi[ks], kk.x, kk.y);
            }
        }
        __syncthreads();

        if (t < NT - 1) {
            const char* ksrc = gk + (size_t)(t + 1) * 2304 * 8;
#pragma unroll
            for (int i = 0; i < 9; i++) {
                int off = (tid + 128 * i) * 16;
                CP16(KPA + off, ksrc + off);
            }
            CP_COMMIT();
        }

        if (t == NT - 1) {
#pragma unroll
            for (int nb = 0; nb < 8; nb++) {
                int c = 1024 + nb * 8 + 2 * tig;
                if (c >= SEQL)     { s_[nb][0] = -INFINITY; s_[nb][2] = -INFINITY; }
                if (c + 1 >= SEQL) { s_[nb][1] = -INFINITY; s_[nb][3] = -INFINITY; }
            }
        }

        float rm0 = -INFINITY, rm1 = -INFINITY;
#pragma unroll
        for (int nb = 0; nb < 8; nb++) {
            rm0 = fmaxf(rm0, fmaxf(s_[nb][0], s_[nb][1]));
            rm1 = fmaxf(rm1, fmaxf(s_[nb][2], s_[nb][3]));
        }
        rm0 = fmaxf(rm0, __shfl_xor_sync(0xffffffffu, rm0, 1));
        rm0 = fmaxf(rm0, __shfl_xor_sync(0xffffffffu, rm0, 2));
        rm1 = fmaxf(rm1, __shfl_xor_sync(0xffffffffu, rm1, 1));
        rm1 = fmaxf(rm1, __shfl_xor_sync(0xffffffffu, rm1, 2));
        float nm0 = fmaxf(m0, rm0), nm1 = fmaxf(m1, rm1);
        float corr0 = __expf(m0 - nm0), corr1 = __expf(m1 - nm1);
        m0 = nm0; m1 = nm1;

        float rs0 = 0.f, rs1 = 0.f;
#pragma unroll
        for (int nb = 0; nb < 8; nb++) {
            s_[nb][0] = __expf(s_[nb][0] - m0);
            s_[nb][1] = __expf(s_[nb][1] - m0);
            s_[nb][2] = __expf(s_[nb][2] - m1);
            s_[nb][3] = __expf(s_[nb][3] - m1);
            rs0 += s_[nb][0] + s_[nb][1];
            rs1 += s_[nb][2] + s_[nb][3];
        }
        rs0 += __shfl_xor_sync(0xffffffffu, rs0, 1);
        rs0 += __shfl_xor_sync(0xffffffffu, rs0, 2);
        rs1 += __shfl_xor_sync(0xffffffffu, rs1, 1);
        rs1 += __shfl_xor_sync(0xffffffffu, rs1, 2);
        l0 = l0 * corr0 + rs0;
        l1 = l1 * corr1 + rs1;

#pragma unroll
        for (int nb = 0; nb < 8; nb++) {
            o[nb][0] *= corr0; o[nb][1] *= corr0;
            o[nb][2] *= corr1; o[nb][3] *= corr1;
        }

#pragma unroll
        for (int nb = 0; nb < 8; nb++) {
            *(float2*)(Ps + (wrow + g) * 68 + nb * 8 + 2 * tig)     = make_float2(s_[nb][0], s_[nb][1]);
            *(float2*)(Ps + (wrow + g + 8) * 68 + nb * 8 + 2 * tig) = make_float2(s_[nb][2], s_[nb][3]);
        }
        __syncwarp();

        uint2* Vp2 = (uint2*)(sm + ((t & 1) ? V1_OFF : V0_OFF));
#pragma unroll
        for (int ks = 0; ks < 8; ks++) {
            uint32_t pa[4];
            pa[0] = f2tf32(Ps[(wrow + g) * 68 + 8 * ks + tig]);
            pa[1] = f2tf32(Ps[(wrow + g + 8) * 68 + 8 * ks + tig]);
            pa[2] = f2tf32(Ps[(wrow + g) * 68 + 8 * ks + tig + 4]);
            pa[3] = f2tf32(Ps[(wrow + g + 8) * 68 + 8 * ks + tig + 4]);
#pragma unroll
            for (int nb = 0; nb < 8; nb++) {
                uint2 vv = Vp2[(nb * 8 + g) * 36 + ks * 4 + tig];
                mma_tf32(o[nb], pa, vv.x, vv.y);
            }
        }
    }

    float inv0 = 1.0f / l0, inv1 = 1.0f / l1;
    int b = bh / HDS, h = bh % HDS;
    int s0 = qb * 64 + wrow + g;
    int s1 = s0 + 8;
#pragma unroll
    for (int nb = 0; nb < 8; nb++) {
        int cc = nb * 8 + 2 * tig;
        if (s0 < SEQL) {
            float* dst = g_ao + ((size_t)b * SEQL + s0) * EMB + h * HD + cc;
            *(float2*)dst = make_float2(o[nb][0] * inv0, o[nb][1] * inv0);
        }
        if (s1 < SEQL) {
            float* dst = g_ao + ((size_t)b * SEQL + s1) * EMB + h * HD + cc;
            *(float2*)dst = make_float2(o[nb][2] * inv1, o[nb][3] * inv1);
        }
    }
}

// ===================== launch =====================
extern "C" void kernel_launch(void* const* d_in, const int* in_sizes, int n_in,
                              void* d_out, int out_size)
{
    const float* x  = (const float*)d_in[0];
    const float* Wq = (const float*)d_in[1];
    const float* Wk = (const float*)d_in[2];
    const float* Wv = (const float*)d_in[3];
    const float* Wo = (const float*)d_in[4];
    const float* bo = (const float*)d_in[5];
    float* out = (float*)d_out;

    double xg = 2.0;
    for (int it = 0; it < 10; ++it) xg = pow(1.0 + xg, 1.0 / 3.0);
    float inv_g = (float)(1.0 / xg);

    cudaFuncSetAttribute(attn_mma_kernel,
                         cudaFuncAttributeMaxDynamicSharedMemorySize, ATTN_SMEM);
    cudaFuncSetAttribute(qkv_mma_kernel,
                         cudaFuncAttributeMaxDynamicSharedMemorySize, GEMM_SMEM);
    cudaFuncSetAttribute(proj_mma_kernel,
                         cudaFuncAttributeMaxDynamicSharedMemorySize, GEMM_SMEM);

    init_freqs<<<1, 192>>>(inv_g);
    init_trig<<<(SEQL * HDS * NF + 255) / 256, 256>>>();
    pack_w_kernel<<<(4 * 72 * 256 + 255) / 256, 256>>>(Wq, Wk, Wv, Wo);

    dim3 qkv_grid((ROWS + 127) / 128, HDS, 3);
    qkv_mma_kernel<<<qkv_grid, 128, GEMM_SMEM>>>(x);

    dim3 attn_grid(NT, BHN);
    attn_mma_kernel<<<attn_grid, 128, ATTN_SMEM>>>();

    dim3 proj_grid((ROWS + 127) / 128, EMB / 64);
    proj_mma_kernel<<<proj_grid, 128, GEMM_SMEM>>>(bo, out);
}